// round 10
// baseline (speedup 1.0000x reference)
#include <cuda_runtime.h>
#include <cuda_bf16.h>
#include <cstdint>

#define DIN 1024
#define DH  256
#define NC  8
#define NMAX 65536

#define BM 128          // rows per CTA
#define BNC 128         // cols per CTA
#define BK 64
#define NT 256
#define CHUNKS (DIN / BK)   // 16
#define SPS 132

// ---------------- device scratch ----------------
__device__ float g_csum[NC * DH];
__device__ int   g_cnt[NC];
__device__ int   g_off[NC];
__device__ int   g_perm[NMAX];
__device__ int   g_scid[NMAX];
__device__ __align__(16) __nv_bfloat16 g_w1bf[DH * DIN];

// ---------------- helpers ----------------
__device__ __forceinline__ uint32_t smem_to_u32(const void* p) {
    uint32_t a;
    asm("{ .reg .u64 t; cvta.to.shared.u64 t, %1; cvt.u32.u64 %0, t; }"
        : "=r"(a) : "l"(p));
    return a;
}
#define CP_ASYNC16(dst, src) \
    asm volatile("cp.async.cg.shared.global [%0], [%1], 16;" :: "r"(dst), "l"(src) : "memory")
#define CP_COMMIT() asm volatile("cp.async.commit_group;" ::: "memory")
#define CP_WAIT0()  asm volatile("cp.async.wait_group 0;" ::: "memory")
#define CP_WAIT1()  asm volatile("cp.async.wait_group 1;" ::: "memory")
#define LDSM4(r0, r1, r2, r3, a) \
    asm volatile("ldmatrix.sync.aligned.m8n8.x4.shared.b16 {%0,%1,%2,%3}, [%4];" \
                 : "=r"(r0), "=r"(r1), "=r"(r2), "=r"(r3) : "r"(a))
#define MMA16816(d0,d1,d2,d3, a0,a1,a2,a3, b0,b1) \
    asm volatile("mma.sync.aligned.m16n8k16.row.col.f32.bf16.bf16.f32 " \
                 "{%0,%1,%2,%3}, {%4,%5,%6,%7}, {%8,%9}, {%0,%1,%2,%3};\n" \
                 : "+f"(d0), "+f"(d1), "+f"(d2), "+f"(d3) \
                 : "r"(a0), "r"(a1), "r"(a2), "r"(a3), "r"(b0), "r"(b1))

// ---------------- k_prep: W1->bf16 (blocks 0..255) + cluster count (256..383) ----------------
__global__ void k_prep(const float* __restrict__ W1, const int* __restrict__ cid, int n) {
    if (blockIdx.x < 256) {
        int base = blockIdx.x * 1024 + threadIdx.x;
#pragma unroll
        for (int t = 0; t < 4; t++) {
            int i = base + t * 256;
            g_w1bf[i] = __float2bfloat16(W1[i]);
        }
    } else {
        __shared__ int h[NC];
        if (threadIdx.x < NC) h[threadIdx.x] = 0;
        __syncthreads();
        int b = blockIdx.x - 256;
        for (int i = b * 256 + threadIdx.x; i < n; i += 128 * 256)
            atomicAdd(&h[cid[i]], 1);
        __syncthreads();
        if (threadIdx.x < NC) atomicAdd(&g_cnt[threadIdx.x], h[threadIdx.x]);
    }
}

__global__ void k_prefix() {
    if (threadIdx.x == 0) {
        int s = 0;
        for (int c = 0; c < NC; c++) { g_off[c] = s; s += g_cnt[c]; }
    }
}

// ---------------- k_scatter: permutation indices only (no data copy) ----------------
__global__ __launch_bounds__(128)
void k_scatter(const int* __restrict__ cid, int n) {
    __shared__ int lh[NC], base[NC], lr[NC];
    const int tid = threadIdx.x;
    int i = blockIdx.x * 128 + tid;
    int c = (i < n) ? cid[i] : -1;
    if (tid < NC) { lh[tid] = 0; lr[tid] = 0; }
    __syncthreads();
    if (c >= 0) atomicAdd(&lh[c], 1);
    __syncthreads();
    if (tid < NC && lh[tid] > 0)
        base[tid] = atomicAdd(&g_off[tid], lh[tid]);
    __syncthreads();
    if (c >= 0) {
        int r = atomicAdd(&lr[c], 1);
        int s = base[c] + r;
        g_perm[s] = i;
        g_scid[s] = c;
    }
}

// ---------------- k_main: coalesced reg-gather fp32 X + reg convert + mma.sync ----------------
// smem layout (bytes)
#define OFF_B1S  0          // 128 floats = 512
#define OFF_CIDS 512        // 128 ints
#define OFF_PERM 1024       // 128 ints
#define OFF_SPRT 1536       // NC*SPS*4 = 4224 -> ends 5760
#define OFF_A    8192       // bf16 A: 2 stages x 16384 -> ends 40960
#define OFF_B    40960      // bf16 B: 2 stages x 16384 -> ends 73728
#define A_STAGE  16384
#define B_STAGE  16384
#define SMEM_BYTES 73728

__global__ __launch_bounds__(NT, 2)
void k_main(const float* __restrict__ X, const float* __restrict__ b1, int n)
{
    extern __shared__ __align__(1024) char smem[];
    const uint32_t sb = smem_to_u32(smem);
    const int tid  = threadIdx.x;
    const int lane = tid & 31;
    const int wid  = tid >> 5;
    const int wm   = wid & 3;      // 4 warps along M (32 rows)
    const int wn   = wid >> 2;     // 2 warps along N (64 cols)
    const int rowBase = (blockIdx.x >> 1) * BM;
    const int colBase = (blockIdx.x & 1) * BNC;

    float* b1s   = (float*)(smem + OFF_B1S);
    int*   cids  = (int*)(smem + OFF_CIDS);
    int*   perms = (int*)(smem + OFF_PERM);
    float* spart = (float*)(smem + OFF_SPRT);

    for (int i = tid; i < NC * SPS; i += NT) spart[i] = 0.f;
    if (tid < BNC) b1s[tid] = b1[colBase + tid];
    if (tid < BM) {
        int g = rowBase + tid;
        int ok = (g < n);
        perms[tid] = ok ? g_perm[g] : 0;
        cids[tid]  = ok ? g_scid[g] : 0;
    }
    __syncthreads();

    // ---- X map: 16 lanes per row-chunk; c16 fixed per thread; 8 rows, 16 apart ----
    const int c16  = tid & 15;     // which float4 within the 64-float chunk
    const int rsub = tid >> 4;     // 0..15
    int prow[8];
    uint32_t xdst[8];
#pragma unroll
    for (int p = 0; p < 8; p++) {
        int row = p * 16 + rsub;
        prow[p] = perms[row];
        xdst[p] = sb + OFF_A + row * 128 +
                  ((((c16 >> 1) ^ (row & 7)) << 4) + ((c16 & 1) << 3));
    }

    // ---- B cp.async maps: 4 units of 16B per thread ----
    const char* bSrc[4];
    uint32_t bDst[4];
#pragma unroll
    for (int i = 0; i < 4; i++) {
        int u = i * NT + tid;
        int row = u >> 3, seg = u & 7;
        bSrc[i] = (const char*)(g_w1bf + (size_t)(colBase + row) * DIN + seg * 8);
        bDst[i] = sb + OFF_B + row * 128 + ((seg ^ (row & 7)) << 4);
    }

    auto ldx = [&](int chunk, uint32_t h[16]) {
#pragma unroll
        for (int half = 0; half < 2; half++) {
            float4 f[4];
#pragma unroll
            for (int p = 0; p < 4; p++) {
                int pp = half * 4 + p;
                f[p] = *(const float4*)(X + (size_t)prow[pp] * DIN +
                                        chunk * BK + c16 * 4);
            }
#pragma unroll
            for (int p = 0; p < 4; p++) {
                __nv_bfloat162 lo = __floats2bfloat162_rn(f[p].x, f[p].y);
                __nv_bfloat162 hi = __floats2bfloat162_rn(f[p].z, f[p].w);
                h[(half * 4 + p) * 2]     = *(uint32_t*)&lo;
                h[(half * 4 + p) * 2 + 1] = *(uint32_t*)&hi;
            }
        }
    };
    auto stx = [&](int st, const uint32_t h[16]) {
#pragma unroll
        for (int p = 0; p < 8; p++)
            asm volatile("st.shared.v2.b32 [%0], {%1,%2};" ::
                "r"(xdst[p] + st * A_STAGE), "r"(h[p*2]), "r"(h[p*2+1]) : "memory");
    };
    auto issueB = [&](int chunk, int st) {
        const int go = chunk * 128;
#pragma unroll
        for (int i = 0; i < 4; i++)
            CP_ASYNC16(bDst[i] + st * B_STAGE, bSrc[i] + go);
        CP_COMMIT();
    };

    // ---- ldmatrix pointers ----
    uint32_t aPtr[2], bPtr[4];
    {
        int jm   = lane & 7;
        int sel8 = (lane >> 3) & 1;
        int selk = (lane >> 4) & 1;
#pragma unroll
        for (int mt = 0; mt < 2; mt++) {
            int r = wm * 32 + mt * 16 + jm + sel8 * 8;
            aPtr[mt] = sb + OFF_A + r * 128 + ((selk ^ (r & 7)) << 4);
        }
        int jn    = lane & 7;
        int selk2 = (lane >> 3) & 1;
        int seln  = (lane >> 4) & 1;
#pragma unroll
        for (int p = 0; p < 4; p++) {
            int r = wn * 64 + p * 16 + jn + seln * 8;
            bPtr[p] = sb + OFF_B + r * 128 + ((selk2 ^ (r & 7)) << 4);
        }
    }

    float acc[2][8][4];
#pragma unroll
    for (int a = 0; a < 2; a++)
#pragma unroll
        for (int b = 0; b < 8; b++)
#pragma unroll
            for (int c = 0; c < 4; c++) acc[a][b][c] = 0.f;

    auto compute = [&](int stage) {
        const uint32_t aOfs = stage * A_STAGE;
        const uint32_t bOfs = stage * B_STAGE;
#pragma unroll
        for (int kk = 0; kk < 4; kk++) {
            uint32_t af[2][4];
#pragma unroll
            for (int mt = 0; mt < 2; mt++)
                LDSM4(af[mt][0], af[mt][1], af[mt][2], af[mt][3],
                      (aPtr[mt] + aOfs) ^ (kk << 5));
            uint32_t bf[4][4];
#pragma unroll
            for (int p = 0; p < 4; p++)
                LDSM4(bf[p][0], bf[p][1], bf[p][2], bf[p][3],
                      (bPtr[p] + bOfs) ^ (kk << 5));
#pragma unroll
            for (int mt = 0; mt < 2; mt++)
#pragma unroll
                for (int p = 0; p < 4; p++) {
                    MMA16816(acc[mt][2*p][0],   acc[mt][2*p][1],
                             acc[mt][2*p][2],   acc[mt][2*p][3],
                             af[mt][0], af[mt][1], af[mt][2], af[mt][3],
                             bf[p][0], bf[p][1]);
                    MMA16816(acc[mt][2*p+1][0], acc[mt][2*p+1][1],
                             acc[mt][2*p+1][2], acc[mt][2*p+1][3],
                             af[mt][0], af[mt][1], af[mt][2], af[mt][3],
                             bf[p][2], bf[p][3]);
                }
        }
    };

    // ---- prologue: A(0) stored, B(0) in flight ----
    {
        uint32_t h0[16];
        ldx(0, h0);
        stx(0, h0);
        issueB(0, 0);
    }

    // ---- main loop: LDG(X chunk+1) shadows under compute(chunk) ----
    uint32_t h[16];
    for (int chunk = 0; chunk < CHUNKS; chunk++) {
        const int cur = chunk & 1;
        const int nxt = cur ^ 1;
        const bool more = (chunk + 1) < CHUNKS;
        if (more) {
            ldx(chunk + 1, h);      // issue LDG now; lands under compute
            issueB(chunk + 1, nxt);
            CP_WAIT1();             // B(cur) ready; B(nxt) still in flight
        } else {
            CP_WAIT0();
        }
        __syncthreads();            // A(cur)+B(cur) visible; prev compute done
        compute(cur);
        if (more) {
            __syncthreads();        // all warps done reading A(nxt)'s old data
            stx(nxt, h);            // X data has long since arrived
        }
    }

    // ---- epilogue: bias + ReLU + segment-sum ----
    const int g  = lane >> 2;
    const int tg = lane & 3;
    const bool uni = (cids[0] == cids[BM - 1]) && (rowBase + BM <= n);

    if (uni) {
        const int cl = cids[0];
#pragma unroll
        for (int nt = 0; nt < 8; nt++) {
            int c = wn * 64 + nt * 8 + tg * 2;
            float s0 = 0.f, s1 = 0.f;
#pragma unroll
            for (int mt = 0; mt < 2; mt++) {
                s0 += fmaxf(acc[mt][nt][0] + b1s[c], 0.f)
                    + fmaxf(acc[mt][nt][2] + b1s[c], 0.f);
                s1 += fmaxf(acc[mt][nt][1] + b1s[c + 1], 0.f)
                    + fmaxf(acc[mt][nt][3] + b1s[c + 1], 0.f);
            }
#pragma unroll
            for (int o = 4; o < 32; o <<= 1) {
                s0 += __shfl_xor_sync(0xffffffffu, s0, o);
                s1 += __shfl_xor_sync(0xffffffffu, s1, o);
            }
            if (g == 0) {
                atomicAdd(&spart[cl * SPS + c], s0);
                atomicAdd(&spart[cl * SPS + c + 1], s1);
            }
        }
    } else {
#pragma unroll
        for (int mt = 0; mt < 2; mt++) {
            int r0 = wm * 32 + mt * 16 + g;
            int r1 = r0 + 8;
            bool v0 = (rowBase + r0) < n;
            bool v1 = (rowBase + r1) < n;
            int c0 = cids[r0] * SPS;
            int c1 = cids[r1] * SPS;
#pragma unroll
            for (int nt = 0; nt < 8; nt++) {
                int c = wn * 64 + nt * 8 + tg * 2;
                float t;
                t = acc[mt][nt][0] + b1s[c];
                if (v0 && t > 0.f) atomicAdd(&spart[c0 + c], t);
                t = acc[mt][nt][1] + b1s[c + 1];
                if (v0 && t > 0.f) atomicAdd(&spart[c0 + c + 1], t);
                t = acc[mt][nt][2] + b1s[c];
                if (v1 && t > 0.f) atomicAdd(&spart[c1 + c], t);
                t = acc[mt][nt][3] + b1s[c + 1];
                if (v1 && t > 0.f) atomicAdd(&spart[c1 + c + 1], t);
            }
        }
    }
    __syncthreads();
    for (int i = tid; i < NC * BNC; i += NT) {
        int c = i >> 7, j = i & 127;
        float v = spart[c * SPS + j];
        if (v != 0.f) atomicAdd(&g_csum[c * DH + colBase + j], v);
    }
}

// ---------------- k_final: small MLP + gated attention ----------------
__global__ __launch_bounds__(512) void k_final(
    const float* __restrict__ Wf, const float* __restrict__ bfv,
    const float* __restrict__ Wa, const float* __restrict__ ba,
    const float* __restrict__ Wb, const float* __restrict__ bb,
    const float* __restrict__ Wc, const float* __restrict__ bc,
    float* __restrict__ out)
{
    __shared__ float hc[NC][DH];
    __shared__ float hp[NC][DH];
    __shared__ float pA[NC][DH];
    __shared__ float pB[NC][DH];
    __shared__ float asum[NC], wts[NC];

    const int tid = threadIdx.x;
    const int j = tid & 255;
    const int hf = tid >> 8;
    const int lane = tid & 31;

    for (int i = tid; i < NC * DH; i += 512) {
        int c = i >> 8;
        hc[c][i & 255] = g_csum[i] / fmaxf((float)g_cnt[c], 1.f);
    }
    if (tid < NC) asum[tid] = 0.f;
    __syncthreads();

    {
        float p[NC];
#pragma unroll
        for (int c = 0; c < NC; c++) p[c] = 0.f;
        const float4* wrow = (const float4*)(Wf + j * DH + hf * 128);
#pragma unroll 4
        for (int k4 = 0; k4 < 32; k4++) {
            float4 w = wrow[k4];
            int k = hf * 128 + k4 * 4;
#pragma unroll
            for (int c = 0; c < NC; c++) {
                float4 h4 = *(const float4*)&hc[c][k];
                p[c] += w.x * h4.x + w.y * h4.y + w.z * h4.z + w.w * h4.w;
            }
        }
        float* dst = hf ? &pB[0][0] : &pA[0][0];
#pragma unroll
        for (int c = 0; c < NC; c++) dst[c * DH + j] = p[c];
    }
    __syncthreads();

    float hpj[NC];
    if (hf == 0) {
#pragma unroll
        for (int c = 0; c < NC; c++) {
            hpj[c] = fmaxf(pA[c][j] + pB[c][j] + bfv[j], 0.f);
            hp[c][j] = hpj[c];
        }
    }
    __syncthreads();

    {
        const float* w2 = (hf ? Wb : Wa) + j * DH;
        float q[NC];
#pragma unroll
        for (int c = 0; c < NC; c++) q[c] = 0.f;
#pragma unroll 4
        for (int k4 = 0; k4 < 64; k4++) {
            float4 w = ((const float4*)w2)[k4];
#pragma unroll
            for (int c = 0; c < NC; c++) {
                float4 h4 = *(const float4*)&hp[c][k4 * 4];
                q[c] += w.x * h4.x + w.y * h4.y + w.z * h4.z + w.w * h4.w;
            }
        }
        float* dst = hf ? &pB[0][0] : &pA[0][0];
#pragma unroll
        for (int c = 0; c < NC; c++) dst[c * DH + j] = q[c];
    }
    __syncthreads();

    if (hf == 0) {
        float wcj = Wc[j];
#pragma unroll
        for (int c = 0; c < NC; c++) {
            float av = tanhf(pA[c][j] + ba[j]);
            float gv = 1.f / (1.f + __expf(-(pB[c][j] + bb[j])));
            float v = av * gv * wcj;
#pragma unroll
            for (int o = 16; o > 0; o >>= 1)
                v += __shfl_xor_sync(0xffffffffu, v, o);
            if (lane == 0) atomicAdd(&asum[c], v);
        }
    }
    __syncthreads();

    if (tid == 0) {
        float m = -1e30f;
        for (int c = 0; c < NC; c++) m = fmaxf(m, asum[c] + bc[0]);
        float s = 0.f;
        for (int c = 0; c < NC; c++) { wts[c] = __expf(asum[c] + bc[0] - m); s += wts[c]; }
        float inv = 1.f / s;
        for (int c = 0; c < NC; c++) wts[c] *= inv;
    }
    __syncthreads();

    if (hf == 0) {
        float s = 0.f;
#pragma unroll
        for (int c = 0; c < NC; c++) s += wts[c] * hpj[c];
        out[j] = s;
    }
}

// ---------------- launch ----------------
extern "C" void kernel_launch(void* const* d_in, const int* in_sizes, int n_in,
                              void* d_out, int out_size)
{
    const float* X   = (const float*)d_in[0];
    const int*   cid = (const int*)d_in[1];
    const float* W1  = (const float*)d_in[2];
    const float* b1  = (const float*)d_in[3];
    const float* Wf  = (const float*)d_in[4];
    const float* bfv = (const float*)d_in[5];
    const float* Wa  = (const float*)d_in[6];
    const float* ba  = (const float*)d_in[7];
    const float* Wb  = (const float*)d_in[8];
    const float* bb  = (const float*)d_in[9];
    const float* Wc  = (const float*)d_in[10];
    const float* bc  = (const float*)d_in[11];
    float* out = (float*)d_out;
    const int n = in_sizes[1];

    cudaFuncSetAttribute(k_main, cudaFuncAttributeMaxDynamicSharedMemorySize, SMEM_BYTES);

    void *p_csum = nullptr, *p_cnt = nullptr;
    cudaGetSymbolAddress(&p_csum, g_csum);
    cudaGetSymbolAddress(&p_cnt,  g_cnt);
    cudaMemsetAsync(p_csum, 0, sizeof(float) * NC * DH, 0);     // launch 1
    cudaMemsetAsync(p_cnt,  0, sizeof(int) * NC, 0);            // launch 2

    k_prep<<<384, 256>>>(W1, cid, n);                           // launch 3
    k_prefix<<<1, 32>>>();                                      // launch 4
    int sg = (n + 127) / 128;
    k_scatter<<<sg, 128>>>(cid, n);                             // launch 5

    int grid = ((n + BM - 1) / BM) * 2;
    k_main<<<grid, NT, SMEM_BYTES>>>(X, b1, n);                 // launch 6 (profiled)
    k_final<<<1, 512>>>(Wf, bfv, Wa, ba, Wb, bb, Wc, bc, out);  // launch 7
}

// round 15
// speedup vs baseline: 1.3397x; 1.3397x over previous
#include <cuda_runtime.h>
#include <cuda_bf16.h>
#include <cstdint>

#define DIN 1024
#define DH  256
#define NC  8
#define NMAX 65536

#define BM 128          // rows per CTA
#define BNC 128         // cols per CTA
#define BK 64
#define NT 256
#define CHUNKS (DIN / BK)   // 16
#define STAGES 3
#define SPS 132

// ---------------- device scratch ----------------
__device__ float g_csum[NC * DH];
__device__ int   g_cnt[NC];
__device__ int   g_off[NC];
__device__ int   g_perm[NMAX];
__device__ int   g_scid[NMAX];
__device__ __align__(16) __nv_bfloat16 g_w1bf[DH * DIN];
__device__ __align__(16) __nv_bfloat16 g_xbf[(size_t)NMAX * DIN];  // UNpermuted bf16 X

// ---------------- helpers ----------------
__device__ __forceinline__ uint32_t smem_to_u32(const void* p) {
    uint32_t a;
    asm("{ .reg .u64 t; cvta.to.shared.u64 t, %1; cvt.u32.u64 %0, t; }"
        : "=r"(a) : "l"(p));
    return a;
}
#define CP_ASYNC16(dst, src) \
    asm volatile("cp.async.cg.shared.global [%0], [%1], 16;" :: "r"(dst), "l"(src) : "memory")
#define CP_COMMIT() asm volatile("cp.async.commit_group;" ::: "memory")
#define CP_WAITN(N) asm volatile("cp.async.wait_group %0;" :: "n"(N) : "memory")
#define LDSM4(r0, r1, r2, r3, a) \
    asm volatile("ldmatrix.sync.aligned.m8n8.x4.shared.b16 {%0,%1,%2,%3}, [%4];" \
                 : "=r"(r0), "=r"(r1), "=r"(r2), "=r"(r3) : "r"(a))
#define MMA16816(d0,d1,d2,d3, a0,a1,a2,a3, b0,b1) \
    asm volatile("mma.sync.aligned.m16n8k16.row.col.f32.bf16.bf16.f32 " \
                 "{%0,%1,%2,%3}, {%4,%5,%6,%7}, {%8,%9}, {%0,%1,%2,%3};\n" \
                 : "+f"(d0), "+f"(d1), "+f"(d2), "+f"(d3) \
                 : "r"(a0), "r"(a1), "r"(a2), "r"(a3), "r"(b0), "r"(b1))

// ---------------- k_prep: W1->bf16 (blocks 0..255) + cluster count (256..383) ----------------
__global__ void k_prep(const float* __restrict__ W1, const int* __restrict__ cid, int n) {
    if (blockIdx.x < 256) {
        int base = blockIdx.x * 1024 + threadIdx.x;
#pragma unroll
        for (int t = 0; t < 4; t++) {
            int i = base + t * 256;
            g_w1bf[i] = __float2bfloat16(W1[i]);
        }
    } else {
        __shared__ int h[NC];
        if (threadIdx.x < NC) h[threadIdx.x] = 0;
        __syncthreads();
        int b = blockIdx.x - 256;
        for (int i = b * 256 + threadIdx.x; i < n; i += 128 * 256)
            atomicAdd(&h[cid[i]], 1);
        __syncthreads();
        if (threadIdx.x < NC) atomicAdd(&g_cnt[threadIdx.x], h[threadIdx.x]);
    }
}

__global__ void k_prefix() {
    if (threadIdx.x == 0) {
        int s = 0;
        for (int c = 0; c < NC; c++) { g_off[c] = s; s += g_cnt[c]; }
    }
}

// ---------------- k_scatter: permutation indices only (no data copy) ----------------
__global__ __launch_bounds__(128)
void k_scatter(const int* __restrict__ cid, int n) {
    __shared__ int lh[NC], base[NC], lr[NC];
    const int tid = threadIdx.x;
    int i = blockIdx.x * 128 + tid;
    int c = (i < n) ? cid[i] : -1;
    if (tid < NC) { lh[tid] = 0; lr[tid] = 0; }
    __syncthreads();
    if (c >= 0) atomicAdd(&lh[c], 1);
    __syncthreads();
    if (tid < NC && lh[tid] > 0)
        base[tid] = atomicAdd(&g_off[tid], lh[tid]);
    __syncthreads();
    if (c >= 0) {
        int r = atomicAdd(&lr[c], 1);
        int s = base[c] + r;
        g_perm[s] = i;
        g_scid[s] = c;
    }
}

// ---------------- k_xconv: streaming fp32 -> bf16 (UNpermuted, max MLP) ----------------
__global__ __launch_bounds__(256)
void k_xconv(const float* __restrict__ X, int n) {
    const size_t total = (size_t)n * DIN / 8;     // units of 8 floats
    const size_t stride = (size_t)gridDim.x * 256;
    size_t u = (size_t)blockIdx.x * 256 + threadIdx.x;
#pragma unroll 2
    for (; u < total; u += stride) {
        const float4* p = (const float4*)(X + u * 8);
        float4 f0 = p[0];
        float4 f1 = p[1];
        __nv_bfloat162 h0 = __floats2bfloat162_rn(f0.x, f0.y);
        __nv_bfloat162 h1 = __floats2bfloat162_rn(f0.z, f0.w);
        __nv_bfloat162 h2 = __floats2bfloat162_rn(f1.x, f1.y);
        __nv_bfloat162 h3 = __floats2bfloat162_rn(f1.z, f1.w);
        uint4 v;
        v.x = *(uint32_t*)&h0; v.y = *(uint32_t*)&h1;
        v.z = *(uint32_t*)&h2; v.w = *(uint32_t*)&h3;
        *(uint4*)(g_xbf + u * 8) = v;
    }
}

// ---------------- k_main: cp.async 3-stage mma.sync GEMM + ReLU + segment-sum ----------------
// smem layout (bytes)
#define OFF_B1S  0          // 128 floats = 512
#define OFF_CIDS 512        // 128 ints
#define OFF_PERM 1024       // 128 ints
#define OFF_SPRT 1536       // NC*SPS*4 = 4224 -> ends 5760
#define OFF_A    8192       // 3 stages x 16384
#define OFF_B    57344      // 3 stages x 16384
#define A_STAGE  16384
#define B_STAGE  16384
#define SMEM_BYTES 106496

__global__ __launch_bounds__(NT, 2)
void k_main(const float* __restrict__ b1, int n)
{
    extern __shared__ __align__(1024) char smem[];
    const uint32_t sb = smem_to_u32(smem);
    const int tid  = threadIdx.x;
    const int lane = tid & 31;
    const int wid  = tid >> 5;
    const int wm   = wid & 3;      // 4 warps along M (32 rows)
    const int wn   = wid >> 2;     // 2 warps along N (64 cols)
    const int rowBase = (blockIdx.x >> 1) * BM;
    const int colBase = (blockIdx.x & 1) * BNC;

    float* b1s   = (float*)(smem + OFF_B1S);
    int*   cids  = (int*)(smem + OFF_CIDS);
    int*   perms = (int*)(smem + OFF_PERM);
    float* spart = (float*)(smem + OFF_SPRT);

    for (int i = tid; i < NC * SPS; i += NT) spart[i] = 0.f;
    if (tid < BNC) b1s[tid] = b1[colBase + tid];
    if (tid < BM) {
        int g = rowBase + tid;
        int ok = (g < n);
        perms[tid] = ok ? g_perm[g] : 0;
        cids[tid]  = ok ? g_scid[g] : 0;
    }
    __syncthreads();

    // ---- cp.async source/dest maps: 4 units of 16B per thread per tile ----
    const char* aSrc[4];
    const char* bSrc[4];
    uint32_t aDst[4], bDst[4];
#pragma unroll
    for (int i = 0; i < 4; i++) {
        int u = i * NT + tid;
        int row = u >> 3, seg = u & 7;
        aSrc[i] = (const char*)(g_xbf + (size_t)perms[row] * DIN + seg * 8);
        bSrc[i] = (const char*)(g_w1bf + (size_t)(colBase + row) * DIN + seg * 8);
        aDst[i] = sb + OFF_A + row * 128 + ((seg ^ (row & 7)) << 4);
        bDst[i] = sb + OFF_B + row * 128 + ((seg ^ (row & 7)) << 4);
    }

    auto issue = [&](int chunk) {
        const int st = chunk % STAGES;
        const int go = chunk * 128;   // bytes into the K dim (64 bf16)
#pragma unroll
        for (int i = 0; i < 4; i++)
            CP_ASYNC16(aDst[i] + st * A_STAGE, aSrc[i] + go);
#pragma unroll
        for (int i = 0; i < 4; i++)
            CP_ASYNC16(bDst[i] + st * B_STAGE, bSrc[i] + go);
        CP_COMMIT();
    };

    // ---- ldmatrix pointers ----
    uint32_t aPtr[2], bPtr[4];
    {
        int jm   = lane & 7;
        int sel8 = (lane >> 3) & 1;
        int selk = (lane >> 4) & 1;
#pragma unroll
        for (int mt = 0; mt < 2; mt++) {
            int r = wm * 32 + mt * 16 + jm + sel8 * 8;
            aPtr[mt] = sb + OFF_A + r * 128 + ((selk ^ (r & 7)) << 4);
        }
        int jn    = lane & 7;
        int selk2 = (lane >> 3) & 1;
        int seln  = (lane >> 4) & 1;
#pragma unroll
        for (int p = 0; p < 4; p++) {
            int r = wn * 64 + p * 16 + jn + seln * 8;
            bPtr[p] = sb + OFF_B + r * 128 + ((selk2 ^ (r & 7)) << 4);
        }
    }

    float acc[2][8][4];
#pragma unroll
    for (int a = 0; a < 2; a++)
#pragma unroll
        for (int b = 0; b < 8; b++)
#pragma unroll
            for (int c = 0; c < 4; c++) acc[a][b][c] = 0.f;

    auto compute = [&](int stage) {
        const uint32_t aOfs = stage * A_STAGE;
        const uint32_t bOfs = stage * B_STAGE;
#pragma unroll
        for (int kk = 0; kk < 4; kk++) {
            uint32_t af[2][4];
#pragma unroll
            for (int mt = 0; mt < 2; mt++)
                LDSM4(af[mt][0], af[mt][1], af[mt][2], af[mt][3],
                      (aPtr[mt] + aOfs) ^ (kk << 5));
            uint32_t bf[4][4];
#pragma unroll
            for (int p = 0; p < 4; p++)
                LDSM4(bf[p][0], bf[p][1], bf[p][2], bf[p][3],
                      (bPtr[p] + bOfs) ^ (kk << 5));
#pragma unroll
            for (int mt = 0; mt < 2; mt++)
#pragma unroll
                for (int p = 0; p < 4; p++) {
                    MMA16816(acc[mt][2*p][0],   acc[mt][2*p][1],
                             acc[mt][2*p][2],   acc[mt][2*p][3],
                             af[mt][0], af[mt][1], af[mt][2], af[mt][3],
                             bf[p][0], bf[p][1]);
                    MMA16816(acc[mt][2*p+1][0], acc[mt][2*p+1][1],
                             acc[mt][2*p+1][2], acc[mt][2*p+1][3],
                             af[mt][0], af[mt][1], af[mt][2], af[mt][3],
                             bf[p][2], bf[p][3]);
                }
        }
    };

    // ---- prologue: stages 0,1 in flight ----
    issue(0);
    issue(1);

    // ---- main loop: one barrier per chunk; loads run 2 chunks ahead ----
    for (int chunk = 0; chunk < CHUNKS; chunk++) {
        if (chunk + 2 < CHUNKS) CP_WAITN(1); else CP_WAITN(0);
        __syncthreads();
        if (chunk + 2 < CHUNKS) issue(chunk + 2);
        compute(chunk % STAGES);
    }

    // ---- epilogue: bias + ReLU + segment-sum ----
    const int g  = lane >> 2;
    const int tg = lane & 3;
    const bool uni = (cids[0] == cids[BM - 1]) && (rowBase + BM <= n);

    if (uni) {
        const int cl = cids[0];
#pragma unroll
        for (int nt = 0; nt < 8; nt++) {
            int c = wn * 64 + nt * 8 + tg * 2;
            float s0 = 0.f, s1 = 0.f;
#pragma unroll
            for (int mt = 0; mt < 2; mt++) {
                s0 += fmaxf(acc[mt][nt][0] + b1s[c], 0.f)
                    + fmaxf(acc[mt][nt][2] + b1s[c], 0.f);
                s1 += fmaxf(acc[mt][nt][1] + b1s[c + 1], 0.f)
                    + fmaxf(acc[mt][nt][3] + b1s[c + 1], 0.f);
            }
#pragma unroll
            for (int o = 4; o < 32; o <<= 1) {
                s0 += __shfl_xor_sync(0xffffffffu, s0, o);
                s1 += __shfl_xor_sync(0xffffffffu, s1, o);
            }
            if (g == 0) {
                atomicAdd(&spart[cl * SPS + c], s0);
                atomicAdd(&spart[cl * SPS + c + 1], s1);
            }
        }
    } else {
#pragma unroll
        for (int mt = 0; mt < 2; mt++) {
            int r0 = wm * 32 + mt * 16 + g;
            int r1 = r0 + 8;
            bool v0 = (rowBase + r0) < n;
            bool v1 = (rowBase + r1) < n;
            int c0 = cids[r0] * SPS;
            int c1 = cids[r1] * SPS;
#pragma unroll
            for (int nt = 0; nt < 8; nt++) {
                int c = wn * 64 + nt * 8 + tg * 2;
                float t;
                t = acc[mt][nt][0] + b1s[c];
                if (v0 && t > 0.f) atomicAdd(&spart[c0 + c], t);
                t = acc[mt][nt][1] + b1s[c + 1];
                if (v0 && t > 0.f) atomicAdd(&spart[c0 + c + 1], t);
                t = acc[mt][nt][2] + b1s[c];
                if (v1 && t > 0.f) atomicAdd(&spart[c1 + c], t);
                t = acc[mt][nt][3] + b1s[c + 1];
                if (v1 && t > 0.f) atomicAdd(&spart[c1 + c + 1], t);
            }
        }
    }
    __syncthreads();
    for (int i = tid; i < NC * BNC; i += NT) {
        int c = i >> 7, j = i & 127;
        float v = spart[c * SPS + j];
        if (v != 0.f) atomicAdd(&g_csum[c * DH + colBase + j], v);
    }
}

// ---------------- k_final: small MLP + gated attention ----------------
__global__ __launch_bounds__(512) void k_final(
    const float* __restrict__ Wf, const float* __restrict__ bfv,
    const float* __restrict__ Wa, const float* __restrict__ ba,
    const float* __restrict__ Wb, const float* __restrict__ bb,
    const float* __restrict__ Wc, const float* __restrict__ bc,
    float* __restrict__ out)
{
    __shared__ float hc[NC][DH];
    __shared__ float hp[NC][DH];
    __shared__ float pA[NC][DH];
    __shared__ float pB[NC][DH];
    __shared__ float asum[NC], wts[NC];

    const int tid = threadIdx.x;
    const int j = tid & 255;
    const int hf = tid >> 8;
    const int lane = tid & 31;

    for (int i = tid; i < NC * DH; i += 512) {
        int c = i >> 8;
        hc[c][i & 255] = g_csum[i] / fmaxf((float)g_cnt[c], 1.f);
    }
    if (tid < NC) asum[tid] = 0.f;
    __syncthreads();

    {
        float p[NC];
#pragma unroll
        for (int c = 0; c < NC; c++) p[c] = 0.f;
        const float4* wrow = (const float4*)(Wf + j * DH + hf * 128);
#pragma unroll 4
        for (int k4 = 0; k4 < 32; k4++) {
            float4 w = wrow[k4];
            int k = hf * 128 + k4 * 4;
#pragma unroll
            for (int c = 0; c < NC; c++) {
                float4 h4 = *(const float4*)&hc[c][k];
                p[c] += w.x * h4.x + w.y * h4.y + w.z * h4.z + w.w * h4.w;
            }
        }
        float* dst = hf ? &pB[0][0] : &pA[0][0];
#pragma unroll
        for (int c = 0; c < NC; c++) dst[c * DH + j] = p[c];
    }
    __syncthreads();

    float hpj[NC];
    if (hf == 0) {
#pragma unroll
        for (int c = 0; c < NC; c++) {
            hpj[c] = fmaxf(pA[c][j] + pB[c][j] + bfv[j], 0.f);
            hp[c][j] = hpj[c];
        }
    }
    __syncthreads();

    {
        const float* w2 = (hf ? Wb : Wa) + j * DH;
        float q[NC];
#pragma unroll
        for (int c = 0; c < NC; c++) q[c] = 0.f;
#pragma unroll 4
        for (int k4 = 0; k4 < 64; k4++) {
            float4 w = ((const float4*)w2)[k4];
#pragma unroll
            for (int c = 0; c < NC; c++) {
                float4 h4 = *(const float4*)&hp[c][k4 * 4];
                q[c] += w.x * h4.x + w.y * h4.y + w.z * h4.z + w.w * h4.w;
            }
        }
        float* dst = hf ? &pB[0][0] : &pA[0][0];
#pragma unroll
        for (int c = 0; c < NC; c++) dst[c * DH + j] = q[c];
    }
    __syncthreads();

    if (hf == 0) {
        float wcj = Wc[j];
#pragma unroll
        for (int c = 0; c < NC; c++) {
            float av = tanhf(pA[c][j] + ba[j]);
            float gv = 1.f / (1.f + __expf(-(pB[c][j] + bb[j])));
            float v = av * gv * wcj;
#pragma unroll
            for (int o = 16; o > 0; o >>= 1)
                v += __shfl_xor_sync(0xffffffffu, v, o);
            if (lane == 0) atomicAdd(&asum[c], v);
        }
    }
    __syncthreads();

    if (tid == 0) {
        float m = -1e30f;
        for (int c = 0; c < NC; c++) m = fmaxf(m, asum[c] + bc[0]);
        float s = 0.f;
        for (int c = 0; c < NC; c++) { wts[c] = __expf(asum[c] + bc[0] - m); s += wts[c]; }
        float inv = 1.f / s;
        for (int c = 0; c < NC; c++) wts[c] *= inv;
    }
    __syncthreads();

    if (hf == 0) {
        float s = 0.f;
#pragma unroll
        for (int c = 0; c < NC; c++) s += wts[c] * hpj[c];
        out[j] = s;
    }
}

// ---------------- launch ----------------
extern "C" void kernel_launch(void* const* d_in, const int* in_sizes, int n_in,
                              void* d_out, int out_size)
{
    const float* X   = (const float*)d_in[0];
    const int*   cid = (const int*)d_in[1];
    const float* W1  = (const float*)d_in[2];
    const float* b1  = (const float*)d_in[3];
    const float* Wf  = (const float*)d_in[4];
    const float* bfv = (const float*)d_in[5];
    const float* Wa  = (const float*)d_in[6];
    const float* ba  = (const float*)d_in[7];
    const float* Wb  = (const float*)d_in[8];
    const float* bb  = (const float*)d_in[9];
    const float* Wc  = (const float*)d_in[10];
    const float* bc  = (const float*)d_in[11];
    float* out = (float*)d_out;
    const int n = in_sizes[1];

    cudaFuncSetAttribute(k_main, cudaFuncAttributeMaxDynamicSharedMemorySize, SMEM_BYTES);

    void *p_csum = nullptr, *p_cnt = nullptr;
    cudaGetSymbolAddress(&p_csum, g_csum);
    cudaGetSymbolAddress(&p_cnt,  g_cnt);
    cudaMemsetAsync(p_csum, 0, sizeof(float) * NC * DH, 0);     // launch 1
    cudaMemsetAsync(p_cnt,  0, sizeof(int) * NC, 0);            // launch 2

    k_prep<<<384, 256>>>(W1, cid, n);                           // launch 3
    k_prefix<<<1, 32>>>();                                      // launch 4
    int sg = (n + 127) / 128;
    k_scatter<<<sg, 128>>>(cid, n);                             // launch 5
    k_xconv<<<8192, 256>>>(X, n);                               // launch 6

    int grid = ((n + BM - 1) / BM) * 2;
    k_main<<<grid, NT, SMEM_BYTES>>>(b1, n);                    // launch 7
    k_final<<<1, 512>>>(Wf, bfv, Wa, ba, Wb, bb, Wc, bc, out);  // launch 8
}